// round 6
// baseline (speedup 1.0000x reference)
#include <cuda_runtime.h>
#include <cuda_bf16.h>
#include <cuda_fp16.h>

// VEGAS adaptive-map transform.
// Inputs: y [B,16] f32, grid [16,ninc+1] f32, inc [16,ninc] f32, ninc i32
// Output: x [B,16] f32 followed by jac [B] f32.
//
// Layout: one thread per float4-group g (sample b=g>>2, quarter q=g&3).
// Consecutive lanes -> consecutive 16B -> all LDG.128/STG.128 fully coalesced.
//
// Tables (96KB total -> 2 CTAs/SM -> 64 warps/SM):
//   sh  [16][ninc] fp32  = inc (EXACT; jac multiplies 16 of these)
//   sgh [16][ninc] fp16  = grid[d][0..ninc-1] (additive use only; deterministic
//                          x rel-err bound 2^-11 ~ 4.9e-4 < 1e-3)
// Clamp trick: iy = min(iy, ninc-1), dy = t - iy. At y==1: dy==1 so
// x = g[ninc-1]+h[ninc-1] = right edge, jac factor = inc[ninc-1]. No selects.
//
// __launch_bounds__(1024,2) caps regs at 32; loop kept minimal (1 group/iter),
// latency hiding via 16 warps/SMSP instead of per-thread pipelining.

__global__ void __launch_bounds__(1024, 2) vegas_map_d16_kernel(
    const float4* __restrict__ y4,
    const float* __restrict__ grd,
    const float* __restrict__ inc,
    float4* __restrict__ x4,
    float* __restrict__ jac,
    int G,            // B*4 float4 groups
    int ninc)
{
    extern __shared__ char smem_raw[];
    const int tabN = 16 * ninc;
    float*  sh  = reinterpret_cast<float*>(smem_raw);            // h fp32
    __half* sgh = reinterpret_cast<__half*>(smem_raw + tabN * 4); // g fp16

    // h table: identical layout to inc -> straight copy.
    for (int i = threadIdx.x; i < tabN; i += blockDim.x)
        sh[i] = inc[i];
    // g table: grid rows are (ninc+1) long; take first ninc entries, fp16.
    for (int i = threadIdx.x; i < tabN; i += blockDim.x) {
        const int d = i / ninc;
        const int j = i - d * ninc;
        sgh[i] = __float2half_rn(grd[d * (ninc + 1) + j]);
    }
    __syncthreads();

    const float nincf  = (float)ninc;
    const float nincf4 = (nincf * nincf) * (nincf * nincf);
    const int   T      = gridDim.x * blockDim.x;   // total threads (mult of 4)
    const int   lane   = threadIdx.x & 31;
    const int   g0     = blockIdx.x * blockDim.x + threadIdx.x;

    // quarter (g&3) invariant across iterations (T is a multiple of 4)
    const int row0 = ((g0 & 3) * 4) * ninc;        // + j*ninc + iy

    for (int g = g0; g < G; g += T) {
        const float4 yv = y4[g];
        float vin[4] = {yv.x, yv.y, yv.z, yv.w};
        float xs[4];
        float ph = 1.0f;

        #pragma unroll
        for (int j = 0; j < 4; ++j) {
            float t  = vin[j] * nincf;
            int   iy = (int)t;                 // y>=0: trunc == floor
            iy = min(iy, ninc - 1);
            const float dy = t - (float)iy;    // == 1 at y==1 -> exact edge
            const int   a  = row0 + j * ninc + iy;
            const float hv = sh[a];
            const float gv = __half2float(sgh[a]);
            xs[j] = fmaf(hv, dy, gv);
            ph *= hv;
        }
        ph *= nincf4;

        x4[g] = make_float4(xs[0], xs[1], xs[2], xs[3]);

        // combine jacobian across the 4 lanes of this sample
        ph *= __shfl_xor_sync(0xffffffffu, ph, 1);
        ph *= __shfl_xor_sync(0xffffffffu, ph, 2);
        if ((lane & 3) == 0) jac[g >> 2] = ph;
    }
}

// Generic fallback (any D): one thread per sample, tables from global memory.
__global__ void vegas_map_generic_kernel(
    const float* __restrict__ y,
    const float* __restrict__ grd,
    const float* __restrict__ inc,
    float* __restrict__ xout,
    float* __restrict__ jac,
    int B, int D, int ninc)
{
    int b = blockIdx.x * blockDim.x + threadIdx.x;
    if (b >= B) return;
    const float nincf = (float)ninc;
    float p = 1.0f;
    for (int d = 0; d < D; ++d) {
        float t  = y[(size_t)b * D + d] * nincf;
        int   iy = (int)t;
        if (iy > ninc) iy = ninc;
        const bool valid = iy < ninc;
        const float dy   = t - (float)iy;
        const int iyi    = valid ? iy : (ninc - 1);
        const float gv = grd[d * (ninc + 1) + iy];
        const float hv = inc[d * ninc + iyi];
        xout[(size_t)b * D + d] = valid ? fmaf(hv, dy, gv) : gv;
        p *= hv * nincf;
    }
    jac[b] = p;
}

extern "C" void kernel_launch(void* const* d_in, const int* in_sizes, int n_in,
                              void* d_out, int out_size)
{
    const float* y   = (const float*)d_in[0];
    const float* grd = (const float*)d_in[1];
    const float* inc = (const float*)d_in[2];

    const int n_y = in_sizes[0];
    const int n_g = in_sizes[1];
    const int n_i = in_sizes[2];

    const int D    = n_g - n_i;          // D*(ninc+1) - D*ninc
    const int ninc = n_i / D;
    const int B    = n_y / D;

    float* x   = (float*)d_out;
    float* jac = x + (size_t)n_y;

    // h fp32 + g fp16 tables
    const size_t smem = (size_t)(16 * ninc) * (sizeof(float) + sizeof(__half));

    if (D == 16 && smem <= 110 * 1024) {
        cudaFuncSetAttribute(vegas_map_d16_kernel,
                             cudaFuncAttributeMaxDynamicSharedMemorySize,
                             (int)smem);
        int dev = 0;
        cudaGetDevice(&dev);
        int sms = 148;
        cudaDeviceGetAttribute(&sms, cudaDevAttrMultiProcessorCount, dev);

        const int threads = 1024;
        const int nCTA    = sms * 2;             // 2 CTAs/SM -> 64 warps/SM
        const int G       = B * 4;               // float4 groups

        vegas_map_d16_kernel<<<nCTA, threads, smem>>>(
            (const float4*)y, grd, inc, (float4*)x, jac, G, ninc);
    } else {
        const int threads = 256;
        const int blocks  = (B + threads - 1) / threads;
        vegas_map_generic_kernel<<<blocks, threads>>>(
            y, grd, inc, x, jac, B, D, ninc);
    }
}

// round 9
// speedup vs baseline: 1.4748x; 1.4748x over previous
#include <cuda_runtime.h>
#include <cuda_bf16.h>

// VEGAS adaptive-map transform.
// Inputs: y [B,16] f32, grid [16,ninc+1] f32, inc [16,ninc] f32, ninc i32
// Output: x [B,16] f32 followed by jac [B] f32.
//
// Evidence-driven design (R6 post-mortem): kernel is LSU-serialization bound.
//  - lane-per-quarter layout: all LDG.128/STG.128 fully coalesced.
//  - ONE LDS.64 per dim from an interleaved float2 {g,h} fp32 table (exact).
//  - Bank-pair mapped table: element (d=q*4+j, iy) stored at float2-addr
//        j*4*ninc + (iy>>2)*16 + q*4 + (iy&3)
//    -> bank-pair = q*4 + (iy&3). Each quarter's 8 lanes hit a private set of
//    4 bank-pairs: conflict degree ~4.4 -> ~3.4 per LDS.64.
//  - clamp trick: iy=min(iy,ninc-1), dy=t-iy (dy==1 at y==1 -> exact edge).
//  - streaming cache hints on the 128MB y/x/jac streams.
//  - 1024 thr, 1 CTA/SM, 2 groups/iter depth-1 prefetch (fits 64 regs).
// Requires ninc % 4 == 0 for the bank mapping; otherwise generic fallback.

__global__ void __launch_bounds__(1024, 1) vegas_map_d16_kernel(
    const float4* __restrict__ y4,
    const float* __restrict__ grd,
    const float* __restrict__ inc,
    float4* __restrict__ x4,
    float* __restrict__ jac,
    int G,            // B*4 float4 groups
    int ninc, int kfull)
{
    extern __shared__ float2 tab[];        // [4 j][ninc/4][4 q][4] bank-mapped
    const int nincx4 = ninc * 4;           // float2 units per j-block

    // Build bank-mapped table: element (d, iy) -> addr below.
    for (int i = threadIdx.x; i < 16 * ninc; i += blockDim.x) {
        const int d  = i / ninc;
        const int iy = i - d * ninc;
        const int q  = d >> 2;
        const int j  = d & 3;
        const int a  = j * nincx4 + ((iy & ~3) << 2) + q * 4 + (iy & 3);
        tab[a] = make_float2(grd[d * (ninc + 1) + iy],
                             inc[d * ninc + iy]);
    }
    __syncthreads();

    const float nincf  = (float)ninc;
    const float nincf4 = (nincf * nincf) * (nincf * nincf);
    const int   T      = gridDim.x * blockDim.x;     // total threads (mult of 4)
    const int   lane   = threadIdx.x & 31;
    const int   g0     = blockIdx.x * blockDim.x + threadIdx.x;

    // quarter (g&3) invariant across iterations (T is a multiple of 4)
    const int qoff = (g0 & 3) * 4;

    #define PROCESS(YV, GIDX)                                                  \
    {                                                                          \
        float vin[4] = {(YV).x, (YV).y, (YV).z, (YV).w};                       \
        float xs[4];                                                           \
        float ph = 1.0f;                                                       \
        _Pragma("unroll")                                                      \
        for (int j = 0; j < 4; ++j) {                                          \
            float t  = vin[j] * nincf;                                         \
            int   iy = (int)t;                 /* y>=0: trunc == floor */      \
            iy = min(iy, ninc - 1);                                            \
            const float dy = t - (float)iy;    /* ==1 at y==1 -> edge */       \
            const int   a  = j * nincx4 + ((iy & ~3) << 2) + qoff + (iy & 3);  \
            const float2 gh = tab[a];                                          \
            xs[j] = fmaf(gh.y, dy, gh.x);                                      \
            ph *= gh.y;                                                        \
        }                                                                      \
        ph *= nincf4;                                                          \
        __stcs(&x4[(GIDX)], make_float4(xs[0], xs[1], xs[2], xs[3]));          \
        ph *= __shfl_xor_sync(0xffffffffu, ph, 1);                             \
        ph *= __shfl_xor_sync(0xffffffffu, ph, 2);                             \
        if ((lane & 3) == 0) __stcs(&jac[(GIDX) >> 2], ph);                    \
    }

    float4 curA, curB, nxtA, nxtB;
    int g = g0;

    if (kfull > 0) {
        curA = __ldcs(&y4[g]);
        curB = __ldcs(&y4[g + T]);
        for (int k = 0; k < kfull; ++k) {
            const int gn = g + 2 * T;
            if (k + 1 < kfull) {               // depth-1 prefetch
                nxtA = __ldcs(&y4[gn]);
                nxtB = __ldcs(&y4[gn + T]);
            }
            PROCESS(curA, g)
            PROCESS(curB, g + T)
            curA = nxtA;
            curB = nxtB;
            g = gn;
        }
    }

    // guarded tail (< 2T groups remain)
    if (g < G)     { float4 yv = __ldcs(&y4[g]);     PROCESS(yv, g)     }
    if (g + T < G) { float4 yv = __ldcs(&y4[g + T]); PROCESS(yv, g + T) }

    #undef PROCESS
}

// Generic fallback (any D, any ninc): one thread per sample, global tables.
__global__ void vegas_map_generic_kernel(
    const float* __restrict__ y,
    const float* __restrict__ grd,
    const float* __restrict__ inc,
    float* __restrict__ xout,
    float* __restrict__ jac,
    int B, int D, int ninc)
{
    int b = blockIdx.x * blockDim.x + threadIdx.x;
    if (b >= B) return;
    const float nincf = (float)ninc;
    float p = 1.0f;
    for (int d = 0; d < D; ++d) {
        float t  = y[(size_t)b * D + d] * nincf;
        int   iy = (int)t;
        if (iy > ninc) iy = ninc;
        const bool valid = iy < ninc;
        const float dy   = t - (float)iy;
        const int iyi    = valid ? iy : (ninc - 1);
        const float gv = grd[d * (ninc + 1) + iy];
        const float hv = inc[d * ninc + iyi];
        xout[(size_t)b * D + d] = valid ? fmaf(hv, dy, gv) : gv;
        p *= hv * nincf;
    }
    jac[b] = p;
}

extern "C" void kernel_launch(void* const* d_in, const int* in_sizes, int n_in,
                              void* d_out, int out_size)
{
    const float* y   = (const float*)d_in[0];
    const float* grd = (const float*)d_in[1];
    const float* inc = (const float*)d_in[2];

    const int n_y = in_sizes[0];
    const int n_g = in_sizes[1];
    const int n_i = in_sizes[2];

    const int D    = n_g - n_i;          // D*(ninc+1) - D*ninc
    const int ninc = n_i / D;
    const int B    = n_y / D;

    float* x   = (float*)d_out;
    float* jac = x + (size_t)n_y;

    const size_t smem = (size_t)(16 * ninc) * sizeof(float2);

    if (D == 16 && (ninc % 4) == 0 && smem <= 200 * 1024) {
        cudaFuncSetAttribute(vegas_map_d16_kernel,
                             cudaFuncAttributeMaxDynamicSharedMemorySize,
                             (int)smem);
        int dev = 0;
        cudaGetDevice(&dev);
        int sms = 148;
        cudaDeviceGetAttribute(&sms, cudaDevAttrMultiProcessorCount, dev);

        const int threads = 1024;
        const int nCTA    = sms;                 // one wave, 1 CTA/SM
        const int T       = nCTA * threads;
        const int G       = B * 4;               // float4 groups
        const int kfull   = G / (2 * T);         // unguarded iterations

        vegas_map_d16_kernel<<<nCTA, threads, smem>>>(
            (const float4*)y, grd, inc, (float4*)x, jac, G, ninc, kfull);
    } else {
        const int threads = 256;
        const int blocks  = (B + threads - 1) / threads;
        vegas_map_generic_kernel<<<blocks, threads>>>(
            y, grd, inc, x, jac, B, D, ninc);
    }
}